// round 16
// baseline (speedup 1.0000x reference)
#include <cuda_runtime.h>

#define Bn 8
#define Cn 64
#define Hn 64
#define Wn 64

typedef unsigned long long ull;

__device__ __forceinline__ ull pack2(float lo, float hi) {
    ull r; asm("mov.b64 %0, {%1, %2};" : "=l"(r) : "f"(lo), "f"(hi)); return r;
}
__device__ __forceinline__ void unpack2(ull v, float& lo, float& hi) {
    asm("mov.b64 {%0, %1}, %2;" : "=f"(lo), "=f"(hi) : "l"(v));
}
__device__ __forceinline__ ull ffma2(ull a, ull b, ull c) {
    ull d; asm("fma.rn.f32x2 %0, %1, %2, %3;" : "=l"(d) : "l"(a), "l"(b), "l"(c)); return d;
}
// (a.hi, b.lo)
__device__ __forceinline__ ull sp(ull a, ull b) {
    ull r;
    asm("{\n\t.reg .f32 al, ah, bl, bh;\n\t"
        "mov.b64 {al, ah}, %1;\n\t"
        "mov.b64 {bl, bh}, %2;\n\t"
        "mov.b64 %0, {ah, bl};\n\t}"
        : "=l"(r) : "l"(a), "l"(b));
    return r;
}
// (e, b.lo)
__device__ __forceinline__ ull spf(float e, ull b) {
    ull r;
    asm("{\n\t.reg .f32 bl, bh;\n\t"
        "mov.b64 {bl, bh}, %2;\n\t"
        "mov.b64 %0, {%1, bl};\n\t}"
        : "=l"(r) : "f"(e), "l"(b));
    return r;
}
// (a.hi, e)
__device__ __forceinline__ ull spl(ull a, float e) {
    ull r;
    asm("{\n\t.reg .f32 al, ah;\n\t"
        "mov.b64 {al, ah}, %1;\n\t"
        "mov.b64 %0, {ah, %2};\n\t}"
        : "=l"(r) : "l"(a), "f"(e));
    return r;
}

__device__ float g_f1[Bn*64*Hn*Wn];    // conv1 out [b][c][h][w]
__device__ float g_f2t[Bn*32*Wn*Hn];   // conv2 out transposed [b][c][w][h]

// Load a 16-px row segment as 8 aligned pairs + 9 shifted pairs.
__device__ __forceinline__ void load_row(ull* AP, ull* S, const float* rowp,
                                         int s16, bool notfirst, bool notlast)
{
    const float* rp = rowp + s16;
    ulonglong2 q0 = *(const ulonglong2*)(rp);
    ulonglong2 q1 = *(const ulonglong2*)(rp + 4);
    ulonglong2 q2 = *(const ulonglong2*)(rp + 8);
    ulonglong2 q3 = *(const ulonglong2*)(rp + 12);
    AP[0]=q0.x; AP[1]=q0.y; AP[2]=q1.x; AP[3]=q1.y;
    AP[4]=q2.x; AP[5]=q2.y; AP[6]=q3.x; AP[7]=q3.y;
    float eL = notfirst ? rp[-1] : 0.f;
    float eR = notlast  ? rp[16] : 0.f;
    S[0] = spf(eL, AP[0]);
#pragma unroll
    for (int j = 1; j < 8; j++) S[j] = sp(AP[j-1], AP[j]);
    S[8] = spl(AP[7], eR);
}

// acc[p] += W0*S[p] + W1*AP[p] + W2*S[p+1]
__device__ __forceinline__ void fma_row(ull* acc, const ull* AP, const ull* S,
                                        ull W0, ull W1, ull W2)
{
#pragma unroll
    for (int p = 0; p < 8; p++) {
        acc[p] = ffma2(W0, S[p],   acc[p]);
        acc[p] = ffma2(W1, AP[p],  acc[p]);
        acc[p] = ffma2(W2, S[p+1], acc[p]);
    }
}

// ---------------------------------------------------------------------------
// conv1 (r11 shape): 3x3 64->64, zero pad, bias+PReLU. lane = co.
// Block 256 thr = 8 warps (coHalf x 4 px-segs of 16). 2 out rows per block.
// ---------------------------------------------------------------------------
__global__ __launch_bounds__(256, 2) void conv1_kernel(
    const float* __restrict__ x, const float* __restrict__ wgt,
    const float* __restrict__ bias, const float* __restrict__ alpha)
{
    const int h0 = blockIdx.x * 2, b = blockIdx.y;
    const int tid  = threadIdx.x;
    const int lane = tid & 31;
    const int ww   = tid >> 5;
    const int coH  = ww & 1;
    const int seg  = ww >> 1;            // 0..3
    const int co   = coH*32 + lane;
    const int s16  = seg * 16;
    const bool nf = (seg > 0), nl = (seg < 3);

    __shared__ __align__(16) float sIn[8][4][64];   // [ci][rr][w], rr = h0-1+rr
    __shared__ float sWt[8][9][64];                 // [ci][k][co]

    const int fw_co = tid >> 2, fw_ci0 = (tid & 3) * 2;

    ull acc[2][8];
#pragma unroll
    for (int r = 0; r < 2; r++)
#pragma unroll
        for (int p = 0; p < 8; p++) acc[r][p] = 0ull;

    for (int cb = 0; cb < 8; cb++) {
#pragma unroll
        for (int t = 0; t < 2; t++) {
            const int i  = tid + t*256;
            const int ci = i >> 6, rr = (i >> 4) & 3, c4 = i & 15;
            const int hh = h0 - 1 + rr;
            float4 v = make_float4(0.f, 0.f, 0.f, 0.f);
            if (hh >= 0 && hh < Hn)
                v = *(const float4*)&x[((b*64 + cb*8 + ci)*Hn + hh)*Wn + c4*4];
            *(float4*)&sIn[ci][rr][c4*4] = v;
        }
        {
            const float* wp = wgt + (fw_co*64 + cb*8 + fw_ci0)*9;
#pragma unroll
            for (int cc = 0; cc < 2; cc++)
#pragma unroll
                for (int k = 0; k < 9; k++)
                    sWt[fw_ci0 + cc][k][fw_co] = wp[cc*9 + k];
        }
        __syncthreads();

#pragma unroll 2
        for (int ci = 0; ci < 8; ci++) {
            ull A_AP[8], A_S[9], B_AP[8], B_S[9];
            load_row(A_AP, A_S, &sIn[ci][0][0], s16, nf, nl);
            load_row(B_AP, B_S, &sIn[ci][1][0], s16, nf, nl);
            const float* wr = &sWt[ci][0][co];
            {   // ky = 0
                float v0 = wr[0], v1 = wr[64], v2 = wr[128];
                ull W0 = pack2(v0,v0), W1 = pack2(v1,v1), W2 = pack2(v2,v2);
                fma_row(acc[0], A_AP, A_S, W0, W1, W2);
                fma_row(acc[1], B_AP, B_S, W0, W1, W2);
            }
            load_row(A_AP, A_S, &sIn[ci][2][0], s16, nf, nl);
            {   // ky = 1
                float v0 = wr[192], v1 = wr[256], v2 = wr[320];
                ull W0 = pack2(v0,v0), W1 = pack2(v1,v1), W2 = pack2(v2,v2);
                fma_row(acc[0], B_AP, B_S, W0, W1, W2);
                fma_row(acc[1], A_AP, A_S, W0, W1, W2);
            }
            load_row(B_AP, B_S, &sIn[ci][3][0], s16, nf, nl);
            {   // ky = 2
                float v0 = wr[384], v1 = wr[448], v2 = wr[512];
                ull W0 = pack2(v0,v0), W1 = pack2(v1,v1), W2 = pack2(v2,v2);
                fma_row(acc[0], A_AP, A_S, W0, W1, W2);
                fma_row(acc[1], B_AP, B_S, W0, W1, W2);
            }
        }
        __syncthreads();
    }

    const float bv = bias[co], av = alpha[co];
#pragma unroll
    for (int r = 0; r < 2; r++) {
        float o[16];
#pragma unroll
        for (int p = 0; p < 8; p++) unpack2(acc[r][p], o[2*p], o[2*p+1]);
#pragma unroll
        for (int e = 0; e < 16; e++) {
            float v = o[e] + bv;
            o[e] = v > 0.f ? v : av*v;
        }
        float* op = &g_f1[((b*64 + co)*Hn + h0 + r)*Wn + s16];
#pragma unroll
        for (int q = 0; q < 4; q++)
            *(float4*)(op + 4*q) = make_float4(o[4*q], o[4*q+1], o[4*q+2], o[4*q+3]);
    }
}

// ---------------------------------------------------------------------------
// conv2 (r11 shape): 3x3 64->32, transposed out [b][c][w][h].
// Block 256 thr = 8 warps (2 rowpairs x 4 segs), 4 rows per block.
// ---------------------------------------------------------------------------
__global__ __launch_bounds__(256, 2) void conv2_kernel(
    const float* __restrict__ wgt, const float* __restrict__ bias,
    const float* __restrict__ alpha)
{
    const int h0 = blockIdx.x * 4, b = blockIdx.y;
    const int tid  = threadIdx.x;
    const int lane = tid & 31;        // co
    const int ww   = tid >> 5;
    const int rp2  = ww >> 2;         // rowpair 0..1
    const int seg  = ww & 3;          // 0..3
    const int s16  = seg * 16;
    const bool nf = (seg > 0), nl = (seg < 3);

    __shared__ __align__(16) float sIn[6][8][64];   // [rr][ci][w], rr = h0-1+rr
    __shared__ float sWt[8][9][32];                 // [ci][k][co]

    const int fw_co = tid >> 3, fw_ci = tid & 7;

    ull acc[2][8];
#pragma unroll
    for (int r = 0; r < 2; r++)
#pragma unroll
        for (int p = 0; p < 8; p++) acc[r][p] = 0ull;

    for (int cb = 0; cb < 8; cb++) {
#pragma unroll
        for (int t = 0; t < 3; t++) {
            const int i  = tid + t*256;
            const int rr = i >> 7, ci = (i >> 4) & 7, c4 = i & 15;
            const int hh = h0 - 1 + rr;
            float4 v = make_float4(0.f, 0.f, 0.f, 0.f);
            if (hh >= 0 && hh < Hn)
                v = *(const float4*)&g_f1[((b*64 + cb*8 + ci)*Hn + hh)*Wn + c4*4];
            *(float4*)&sIn[rr][ci][c4*4] = v;
        }
        {
            const float* wp = wgt + (fw_co*64 + cb*8 + fw_ci)*9;
#pragma unroll
            for (int k = 0; k < 9; k++)
                sWt[fw_ci][k][fw_co] = wp[k];
        }
        __syncthreads();

#pragma unroll 2
        for (int ci = 0; ci < 8; ci++) {
            ull A_AP[8], A_S[9], B_AP[8], B_S[9];
            load_row(A_AP, A_S, &sIn[2*rp2 + 0][ci][0], s16, nf, nl);
            load_row(B_AP, B_S, &sIn[2*rp2 + 1][ci][0], s16, nf, nl);
            const float* wr = &sWt[ci][0][lane];
            {
                float v0 = wr[0], v1 = wr[32], v2 = wr[64];
                ull W0 = pack2(v0,v0), W1 = pack2(v1,v1), W2 = pack2(v2,v2);
                fma_row(acc[0], A_AP, A_S, W0, W1, W2);
                fma_row(acc[1], B_AP, B_S, W0, W1, W2);
            }
            load_row(A_AP, A_S, &sIn[2*rp2 + 2][ci][0], s16, nf, nl);
            {
                float v0 = wr[96], v1 = wr[128], v2 = wr[160];
                ull W0 = pack2(v0,v0), W1 = pack2(v1,v1), W2 = pack2(v2,v2);
                fma_row(acc[0], B_AP, B_S, W0, W1, W2);
                fma_row(acc[1], A_AP, A_S, W0, W1, W2);
            }
            load_row(B_AP, B_S, &sIn[2*rp2 + 3][ci][0], s16, nf, nl);
            {
                float v0 = wr[192], v1 = wr[224], v2 = wr[256];
                ull W0 = pack2(v0,v0), W1 = pack2(v1,v1), W2 = pack2(v2,v2);
                fma_row(acc[0], A_AP, A_S, W0, W1, W2);
                fma_row(acc[1], B_AP, B_S, W0, W1, W2);
            }
        }
        __syncthreads();
    }

    const int co = lane;
    const float bv = bias[co], av = alpha[co];
#pragma unroll
    for (int r = 0; r < 2; r++) {
        const int h = h0 + 2*rp2 + r;
#pragma unroll
        for (int p = 0; p < 8; p++) {
            float lo, hi; unpack2(acc[r][p], lo, hi);
            lo += bv; hi += bv;
            lo = lo > 0.f ? lo : av*lo;
            hi = hi > 0.f ? hi : av*hi;
            const int w = s16 + 2*p;
            g_f2t[((b*32 + co)*Wn + w    )*Hn + h] = lo;
            g_f2t[((b*32 + co)*Wn + w + 1)*Hn + h] = hi;
        }
    }
}

// ---------------------------------------------------------------------------
// Fused: 1x1 conv (K=32) + softmax(9) + upsample. NOW 2 w-columns per block.
// 256 thr: pg = tid&15 (4 px), pq = (tid>>4)&3, c_l = tid>>6.
// Per warp-ci: 72 FFMA2 vs 8 wf pixels + 9 wf weights + 9 packs.
// Grid (16 cchunk, 32 wpair, 8 b) = 4096 blocks.
// ---------------------------------------------------------------------------
__global__ __launch_bounds__(256, 2) void fused_kernel(
    const float* __restrict__ xlow, const float* __restrict__ kw,
    const float* __restrict__ kb, float* __restrict__ out)
{
    const int cchunk = blockIdx.x;
    const int w0     = blockIdx.y * 2;
    const int b      = blockIdx.z;
    const int tid = threadIdx.x;
    const int pg  = tid & 15;         // h = pg*4 + j
    const int pq  = (tid >> 4) & 3;
    const int c_l = tid >> 6;

    __shared__ float swt[144*33];                   // plain f32 weights, pad 33
    __shared__ __align__(16) float sf2[2][32*64];   // [col][ci*64+h]
    __shared__ __align__(16) float sx[4][4][68];    // [c_l][dxc][h+1], dxc=w0-1..w0+2
    __shared__ float sbias[144];

    for (int idx = tid; idx < 2*32*64; idx += 256) {
        const int col = idx >> 11, ci = (idx >> 6) & 31, h = idx & 63;
        sf2[col][ci*64 + h] = g_f2t[((b*32 + ci)*Wn + w0 + col)*Hn + h];
    }
    for (int idx = tid; idx < 144*32; idx += 256) {
        int r = idx >> 5, ci = idx & 31;
        swt[r*33 + ci] = kw[(cchunk*144 + r)*32 + ci];
    }
    for (int idx = tid; idx < 144; idx += 256) sbias[idx] = kb[cchunk*144 + idx];
    for (int idx = tid; idx < 4*4*66; idx += 256) {
        int cl  = idx / 264;
        int rem = idx % 264;
        int dxc = rem / 66;
        int hh  = rem % 66;
        int hr = min(max(hh - 1, 0), Hn - 1);
        int wc = min(max(w0 + dxc - 1, 0), Wn - 1);
        sx[cl][dxc][hh] = xlow[((b*Cn + cchunk*4 + cl)*Hn + hr)*Wn + wc];
    }
    __syncthreads();

    ull m[2][9][2];
#pragma unroll
    for (int col = 0; col < 2; col++)
#pragma unroll
        for (int k = 0; k < 9; k++) { m[col][k][0] = 0ull; m[col][k][1] = 0ull; }

    const int rowb = c_l*36 + pq;
    const float* wtb = &swt[rowb*33];

#pragma unroll 4
    for (int ci = 0; ci < 32; ci++) {
        ulonglong2 P0 = *(const ulonglong2*)&sf2[0][ci*64 + pg*4];
        ulonglong2 P1 = *(const ulonglong2*)&sf2[1][ci*64 + pg*4];
        ull W[9];
#pragma unroll
        for (int k = 0; k < 9; k++) {
            float v = wtb[k*132 + ci];   // 132 = 4*33
            W[k] = pack2(v, v);
        }
#pragma unroll
        for (int k = 0; k < 9; k++) {
            m[0][k][0] = ffma2(W[k], P0.x, m[0][k][0]);
            m[0][k][1] = ffma2(W[k], P0.y, m[0][k][1]);
            m[1][k][0] = ffma2(W[k], P1.x, m[1][k][0]);
            m[1][k][1] = ffma2(W[k], P1.y, m[1][k][1]);
        }
    }

    float b9[9];
#pragma unroll
    for (int k = 0; k < 9; k++) b9[k] = sbias[rowb + k*4];

    // neighbor windows: nbd[dxc][0..5], h window = pg*4 + j + dy, dy in 0..2
    float nbd[4][6];
#pragma unroll
    for (int dxc = 0; dxc < 4; dxc++) {
        float4 q0 = *(const float4*)&sx[c_l][dxc][pg*4];
        float2 q2 = *(const float2*)&sx[c_l][dxc][pg*4 + 4];
        nbd[dxc][0]=q0.x; nbd[dxc][1]=q0.y; nbd[dxc][2]=q0.z;
        nbd[dxc][3]=q0.w; nbd[dxc][4]=q2.x; nbd[dxc][5]=q2.y;
    }

    const int c = cchunk*4 + c_l;
    const int p = pq >> 1, q = pq & 1;

#pragma unroll
    for (int col = 0; col < 2; col++) {
        float* orow = &out[((b*Cn + c)*128 + (2*(w0 + col) + q))*128 + p];
#pragma unroll
        for (int jj = 0; jj < 2; jj++) {
            float lo[9], hi[9];
#pragma unroll
            for (int k = 0; k < 9; k++) unpack2(m[col][k][jj], lo[k], hi[k]);
#pragma unroll
            for (int e = 0; e < 2; e++) {
                const int j = 2*jj + e;
                const float* lv = e ? hi : lo;
                float se = 0.f, sv = 0.f;
#pragma unroll
                for (int k = 0; k < 9; k++) {
                    float ex = __expf(lv[k] + b9[k]);   // logits tiny: no max-sub
                    se += ex;
                    sv = fmaf(ex, nbd[(k % 3) + col][j + k/3], sv);
                }
                orow[2*(pg*4 + j)] = sv * __fdividef(1.f, se);
            }
        }
    }
}

extern "C" void kernel_launch(void* const* d_in, const int* in_sizes, int n_in,
                              void* d_out, int out_size)
{
    const float* x_low = (const float*)d_in[0];
    const float* ctx   = (const float*)d_in[1];
    const float* c1_w  = (const float*)d_in[2];
    const float* c1_b  = (const float*)d_in[3];
    const float* p1_a  = (const float*)d_in[4];
    const float* c2_w  = (const float*)d_in[5];
    const float* c2_b  = (const float*)d_in[6];
    const float* p2_a  = (const float*)d_in[7];
    const float* kp_w  = (const float*)d_in[8];
    const float* kp_b  = (const float*)d_in[9];
    float* out = (float*)d_out;

    conv1_kernel<<<dim3(32, 8), 256>>>(ctx, c1_w, c1_b, p1_a);
    conv2_kernel<<<dim3(16, 8), 256>>>(c2_w, c2_b, p2_a);
    fused_kernel<<<dim3(16, 32, 8), 256>>>(x_low, kp_w, kp_b, out);
}

// round 17
// speedup vs baseline: 1.1157x; 1.1157x over previous
#include <cuda_runtime.h>

#define Bn 8
#define Cn 64
#define Hn 64
#define Wn 64

typedef unsigned long long ull;

__device__ __forceinline__ ull pack2(float lo, float hi) {
    ull r; asm("mov.b64 %0, {%1, %2};" : "=l"(r) : "f"(lo), "f"(hi)); return r;
}
__device__ __forceinline__ void unpack2(ull v, float& lo, float& hi) {
    asm("mov.b64 {%0, %1}, %2;" : "=f"(lo), "=f"(hi) : "l"(v));
}
__device__ __forceinline__ ull ffma2(ull a, ull b, ull c) {
    ull d; asm("fma.rn.f32x2 %0, %1, %2, %3;" : "=l"(d) : "l"(a), "l"(b), "l"(c)); return d;
}
// (a.hi, b.lo)
__device__ __forceinline__ ull sp(ull a, ull b) {
    ull r;
    asm("{\n\t.reg .f32 al, ah, bl, bh;\n\t"
        "mov.b64 {al, ah}, %1;\n\t"
        "mov.b64 {bl, bh}, %2;\n\t"
        "mov.b64 %0, {ah, bl};\n\t}"
        : "=l"(r) : "l"(a), "l"(b));
    return r;
}
// (e, b.lo)
__device__ __forceinline__ ull spf(float e, ull b) {
    ull r;
    asm("{\n\t.reg .f32 bl, bh;\n\t"
        "mov.b64 {bl, bh}, %2;\n\t"
        "mov.b64 %0, {%1, bl};\n\t}"
        : "=l"(r) : "f"(e), "l"(b));
    return r;
}
// (a.hi, e)
__device__ __forceinline__ ull spl(ull a, float e) {
    ull r;
    asm("{\n\t.reg .f32 al, ah;\n\t"
        "mov.b64 {al, ah}, %1;\n\t"
        "mov.b64 %0, {ah, %2};\n\t}"
        : "=l"(r) : "l"(a), "f"(e));
    return r;
}

__device__ float g_f1[Bn*64*Hn*Wn];    // conv1 out [b][c][h][w]
__device__ float g_f2t[Bn*32*Wn*Hn];   // conv2 out transposed [b][c][w][h]

// Load a 16-px row segment as 8 aligned pairs + 9 shifted pairs.
__device__ __forceinline__ void load_row(ull* AP, ull* S, const float* rowp,
                                         int s16, bool notfirst, bool notlast)
{
    const float* rp = rowp + s16;
    ulonglong2 q0 = *(const ulonglong2*)(rp);
    ulonglong2 q1 = *(const ulonglong2*)(rp + 4);
    ulonglong2 q2 = *(const ulonglong2*)(rp + 8);
    ulonglong2 q3 = *(const ulonglong2*)(rp + 12);
    AP[0]=q0.x; AP[1]=q0.y; AP[2]=q1.x; AP[3]=q1.y;
    AP[4]=q2.x; AP[5]=q2.y; AP[6]=q3.x; AP[7]=q3.y;
    float eL = notfirst ? rp[-1] : 0.f;
    float eR = notlast  ? rp[16] : 0.f;
    S[0] = spf(eL, AP[0]);
#pragma unroll
    for (int j = 1; j < 8; j++) S[j] = sp(AP[j-1], AP[j]);
    S[8] = spl(AP[7], eR);
}

__device__ __forceinline__ void fma_row(ull* acc, const ull* AP, const ull* S,
                                        ull W0, ull W1, ull W2)
{
#pragma unroll
    for (int p = 0; p < 8; p++) {
        acc[p] = ffma2(W0, S[p],   acc[p]);
        acc[p] = ffma2(W1, AP[p],  acc[p]);
        acc[p] = ffma2(W2, S[p+1], acc[p]);
    }
}

// 8-px variants for conv2
__device__ __forceinline__ void load_row8(ull* AP, ull* S, const float* rowp,
                                          int s8, bool nf, bool nl)
{
    const float* rp = rowp + s8;
    ulonglong2 q0 = *(const ulonglong2*)(rp);
    ulonglong2 q1 = *(const ulonglong2*)(rp + 4);
    AP[0]=q0.x; AP[1]=q0.y; AP[2]=q1.x; AP[3]=q1.y;
    float eL = nf ? rp[-1] : 0.f;
    float eR = nl ? rp[8]  : 0.f;
    S[0] = spf(eL, AP[0]);
    S[1] = sp(AP[0], AP[1]);
    S[2] = sp(AP[1], AP[2]);
    S[3] = sp(AP[2], AP[3]);
    S[4] = spl(AP[3], eR);
}

__device__ __forceinline__ void fma_row8(ull* acc, const ull* AP, const ull* S,
                                         ull W0, ull W1, ull W2)
{
#pragma unroll
    for (int p = 0; p < 4; p++) {
        acc[p] = ffma2(W0, S[p],   acc[p]);
        acc[p] = ffma2(W1, AP[p],  acc[p]);
        acc[p] = ffma2(W2, S[p+1], acc[p]);
    }
}

// ---------------------------------------------------------------------------
// conv1 (r11, best known): 3x3 64->64, zero pad, bias+PReLU. lane = co.
// Block 256 thr = 8 warps (coHalf x 4 px-segs of 16). 2 out rows per block.
// ---------------------------------------------------------------------------
__global__ __launch_bounds__(256, 2) void conv1_kernel(
    const float* __restrict__ x, const float* __restrict__ wgt,
    const float* __restrict__ bias, const float* __restrict__ alpha)
{
    const int h0 = blockIdx.x * 2, b = blockIdx.y;
    const int tid  = threadIdx.x;
    const int lane = tid & 31;
    const int ww   = tid >> 5;
    const int coH  = ww & 1;
    const int seg  = ww >> 1;            // 0..3
    const int co   = coH*32 + lane;
    const int s16  = seg * 16;
    const bool nf = (seg > 0), nl = (seg < 3);

    __shared__ __align__(16) float sIn[8][4][64];   // [ci][rr][w], rr = h0-1+rr
    __shared__ float sWt[8][9][64];                 // [ci][k][co]

    const int fw_co = tid >> 2, fw_ci0 = (tid & 3) * 2;

    ull acc[2][8];
#pragma unroll
    for (int r = 0; r < 2; r++)
#pragma unroll
        for (int p = 0; p < 8; p++) acc[r][p] = 0ull;

    for (int cb = 0; cb < 8; cb++) {
#pragma unroll
        for (int t = 0; t < 2; t++) {
            const int i  = tid + t*256;
            const int ci = i >> 6, rr = (i >> 4) & 3, c4 = i & 15;
            const int hh = h0 - 1 + rr;
            float4 v = make_float4(0.f, 0.f, 0.f, 0.f);
            if (hh >= 0 && hh < Hn)
                v = *(const float4*)&x[((b*64 + cb*8 + ci)*Hn + hh)*Wn + c4*4];
            *(float4*)&sIn[ci][rr][c4*4] = v;
        }
        {
            const float* wp = wgt + (fw_co*64 + cb*8 + fw_ci0)*9;
#pragma unroll
            for (int cc = 0; cc < 2; cc++)
#pragma unroll
                for (int k = 0; k < 9; k++)
                    sWt[fw_ci0 + cc][k][fw_co] = wp[cc*9 + k];
        }
        __syncthreads();

#pragma unroll 2
        for (int ci = 0; ci < 8; ci++) {
            ull A_AP[8], A_S[9], B_AP[8], B_S[9];
            load_row(A_AP, A_S, &sIn[ci][0][0], s16, nf, nl);
            load_row(B_AP, B_S, &sIn[ci][1][0], s16, nf, nl);
            const float* wr = &sWt[ci][0][co];
            {   // ky = 0
                float v0 = wr[0], v1 = wr[64], v2 = wr[128];
                ull W0 = pack2(v0,v0), W1 = pack2(v1,v1), W2 = pack2(v2,v2);
                fma_row(acc[0], A_AP, A_S, W0, W1, W2);
                fma_row(acc[1], B_AP, B_S, W0, W1, W2);
            }
            load_row(A_AP, A_S, &sIn[ci][2][0], s16, nf, nl);
            {   // ky = 1
                float v0 = wr[192], v1 = wr[256], v2 = wr[320];
                ull W0 = pack2(v0,v0), W1 = pack2(v1,v1), W2 = pack2(v2,v2);
                fma_row(acc[0], B_AP, B_S, W0, W1, W2);
                fma_row(acc[1], A_AP, A_S, W0, W1, W2);
            }
            load_row(B_AP, B_S, &sIn[ci][3][0], s16, nf, nl);
            {   // ky = 2
                float v0 = wr[384], v1 = wr[448], v2 = wr[512];
                ull W0 = pack2(v0,v0), W1 = pack2(v1,v1), W2 = pack2(v2,v2);
                fma_row(acc[0], A_AP, A_S, W0, W1, W2);
                fma_row(acc[1], B_AP, B_S, W0, W1, W2);
            }
        }
        __syncthreads();
    }

    const float bv = bias[co], av = alpha[co];
#pragma unroll
    for (int r = 0; r < 2; r++) {
        float o[16];
#pragma unroll
        for (int p = 0; p < 8; p++) unpack2(acc[r][p], o[2*p], o[2*p+1]);
#pragma unroll
        for (int e = 0; e < 16; e++) {
            float v = o[e] + bv;
            o[e] = v > 0.f ? v : av*v;
        }
        float* op = &g_f1[((b*64 + co)*Hn + h0 + r)*Wn + s16];
#pragma unroll
        for (int q = 0; q < 4; q++)
            *(float4*)(op + 4*q) = make_float4(o[4*q], o[4*q+1], o[4*q+2], o[4*q+3]);
    }
}

// ---------------------------------------------------------------------------
// conv2: 3x3 64->32, zero pad, bias+PReLU, transposed out [b][c][w][h].
// NOW 8-px warps, 2-row blocks: warp = 8 px x 2 rows, lane = co.
// Block 256 thr = 8 seg-warps. Grid (32, 8) = 256 blocks, 2048 warps.
// ---------------------------------------------------------------------------
__global__ __launch_bounds__(256, 3) void conv2_kernel(
    const float* __restrict__ wgt, const float* __restrict__ bias,
    const float* __restrict__ alpha)
{
    const int h0 = blockIdx.x * 2, b = blockIdx.y;
    const int tid  = threadIdx.x;
    const int lane = tid & 31;        // co
    const int seg  = tid >> 5;        // 0..7
    const int s8   = seg * 8;
    const bool nf = (seg > 0), nl = (seg < 7);

    __shared__ __align__(16) float sIn[8][4][64];   // [ci][rr][w], rr = h0-1+rr
    __shared__ float sWt[8][9][32];                 // [ci][k][co]

    const int fw_co = tid >> 3, fw_ci = tid & 7;

    ull acc[2][4];
#pragma unroll
    for (int r = 0; r < 2; r++)
#pragma unroll
        for (int p = 0; p < 4; p++) acc[r][p] = 0ull;

    for (int cb = 0; cb < 8; cb++) {
#pragma unroll
        for (int t = 0; t < 2; t++) {
            const int i  = tid + t*256;
            const int ci = i >> 6, rr = (i >> 4) & 3, c4 = i & 15;
            const int hh = h0 - 1 + rr;
            float4 v = make_float4(0.f, 0.f, 0.f, 0.f);
            if (hh >= 0 && hh < Hn)
                v = *(const float4*)&g_f1[((b*64 + cb*8 + ci)*Hn + hh)*Wn + c4*4];
            *(float4*)&sIn[ci][rr][c4*4] = v;
        }
        {
            const float* wp = wgt + (fw_co*64 + cb*8 + fw_ci)*9;
#pragma unroll
            for (int k = 0; k < 9; k++)
                sWt[fw_ci][k][fw_co] = wp[k];
        }
        __syncthreads();

#pragma unroll 2
        for (int ci = 0; ci < 8; ci++) {
            ull A_AP[4], A_S[5], B_AP[4], B_S[5];
            load_row8(A_AP, A_S, &sIn[ci][0][0], s8, nf, nl);
            load_row8(B_AP, B_S, &sIn[ci][1][0], s8, nf, nl);
            const float* wr = &sWt[ci][0][lane];
            {   // ky = 0
                float v0 = wr[0], v1 = wr[32], v2 = wr[64];
                ull W0 = pack2(v0,v0), W1 = pack2(v1,v1), W2 = pack2(v2,v2);
                fma_row8(acc[0], A_AP, A_S, W0, W1, W2);
                fma_row8(acc[1], B_AP, B_S, W0, W1, W2);
            }
            load_row8(A_AP, A_S, &sIn[ci][2][0], s8, nf, nl);
            {   // ky = 1
                float v0 = wr[96], v1 = wr[128], v2 = wr[160];
                ull W0 = pack2(v0,v0), W1 = pack2(v1,v1), W2 = pack2(v2,v2);
                fma_row8(acc[0], B_AP, B_S, W0, W1, W2);
                fma_row8(acc[1], A_AP, A_S, W0, W1, W2);
            }
            load_row8(B_AP, B_S, &sIn[ci][3][0], s8, nf, nl);
            {   // ky = 2
                float v0 = wr[192], v1 = wr[224], v2 = wr[256];
                ull W0 = pack2(v0,v0), W1 = pack2(v1,v1), W2 = pack2(v2,v2);
                fma_row8(acc[0], A_AP, A_S, W0, W1, W2);
                fma_row8(acc[1], B_AP, B_S, W0, W1, W2);
            }
        }
        __syncthreads();
    }

    const int co = lane;
    const float bv = bias[co], av = alpha[co];
#pragma unroll
    for (int r = 0; r < 2; r++) {
        const int h = h0 + r;
#pragma unroll
        for (int p = 0; p < 4; p++) {
            float lo, hi; unpack2(acc[r][p], lo, hi);
            lo += bv; hi += bv;
            lo = lo > 0.f ? lo : av*lo;
            hi = hi > 0.f ? hi : av*hi;
            const int w = s8 + 2*p;
            g_f2t[((b*32 + co)*Wn + w    )*Hn + h] = lo;
            g_f2t[((b*32 + co)*Wn + w + 1)*Hn + h] = hi;
        }
    }
}

// ---------------------------------------------------------------------------
// Fused (r11 + bias-preload): 1x1 conv (K=32) + softmax(9) + upsample.
// 128 thr, 8192 blocks. Thread = (c_l, pq, pg): 9 logits x 8 h-pixels.
// ---------------------------------------------------------------------------
__global__ __launch_bounds__(128, 4) void fused_kernel(
    const float* __restrict__ xlow, const float* __restrict__ kw,
    const float* __restrict__ kb, float* __restrict__ out)
{
    const int cchunk = blockIdx.x;
    const int w      = blockIdx.y;
    const int b      = blockIdx.z;
    const int tid = threadIdx.x;
    const int pg  = tid & 7;
    const int pq  = (tid >> 3) & 3;
    const int c_l = tid >> 5;

    __shared__ float swt[144*33];                  // plain f32 weights, pad 33
    __shared__ __align__(16) float sf2[32*64];     // [ci][h]
    __shared__ __align__(16) float sx[4][3][68];   // edge-clamped x_low patch
    __shared__ float sbias[144];

    for (int idx = tid; idx < 32*64; idx += 128)
        sf2[idx] = g_f2t[((b*32 + (idx >> 6))*Wn + w)*Hn + (idx & 63)];
    for (int idx = tid; idx < 144*32; idx += 128) {
        int r = idx >> 5, ci = idx & 31;
        swt[r*33 + ci] = kw[(cchunk*144 + r)*32 + ci];
    }
    for (int idx = tid; idx < 144; idx += 128) sbias[idx] = kb[cchunk*144 + idx];
    for (int idx = tid; idx < 4*3*66; idx += 128) {
        int cl = idx / 198;
        int dx = (idx % 198) / 66;
        int hh = idx % 66;
        int hr = min(max(hh - 1, 0), Hn - 1);
        int wc = min(max(w + dx - 1, 0), Wn - 1);
        sx[cl][dx][hh] = xlow[((b*Cn + cchunk*4 + cl)*Hn + hr)*Wn + wc];
    }
    __syncthreads();

    const int rowb = c_l*36 + pq;

    // bias folded into accumulator init
    ull m[9][4];
#pragma unroll
    for (int k = 0; k < 9; k++) {
        float bk = sbias[rowb + k*4];
        ull bi = pack2(bk, bk);
#pragma unroll
        for (int j = 0; j < 4; j++) m[k][j] = bi;
    }

    const float* wtb = &swt[rowb*33];

#pragma unroll 4
    for (int ci = 0; ci < 32; ci++) {
        ulonglong2 p01 = *(const ulonglong2*)&sf2[ci*64 + pg*8];
        ulonglong2 p23 = *(const ulonglong2*)&sf2[ci*64 + pg*8 + 4];
        ull P[4] = {p01.x, p01.y, p23.x, p23.y};
        ull W[9];
#pragma unroll
        for (int k = 0; k < 9; k++) {
            float v = wtb[k*132 + ci];   // 132 = 4*33
            W[k] = pack2(v, v);
        }
#pragma unroll
        for (int k = 0; k < 9; k++)
#pragma unroll
            for (int j = 0; j < 4; j++) m[k][j] = ffma2(W[k], P[j], m[k][j]);
    }

    float nbd[3][10];
#pragma unroll
    for (int dx = 0; dx < 3; dx++) {
        float4 q0 = *(const float4*)&sx[c_l][dx][pg*8];
        float4 q1 = *(const float4*)&sx[c_l][dx][pg*8 + 4];
        float2 q2 = *(const float2*)&sx[c_l][dx][pg*8 + 8];
        nbd[dx][0]=q0.x; nbd[dx][1]=q0.y; nbd[dx][2]=q0.z; nbd[dx][3]=q0.w;
        nbd[dx][4]=q1.x; nbd[dx][5]=q1.y; nbd[dx][6]=q1.z; nbd[dx][7]=q1.w;
        nbd[dx][8]=q2.x; nbd[dx][9]=q2.y;
    }

    const int c = cchunk*4 + c_l;
    const int p = pq >> 1, q = pq & 1;
    float* orow = &out[((b*Cn + c)*128 + (2*w + q))*128 + p];

#pragma unroll
    for (int jj = 0; jj < 4; jj++) {
        float lo[9], hi[9];
#pragma unroll
        for (int k = 0; k < 9; k++) unpack2(m[k][jj], lo[k], hi[k]);
#pragma unroll
        for (int e = 0; e < 2; e++) {
            const int j = 2*jj + e;
            const float* lv = e ? hi : lo;
            float se = 0.f, sv = 0.f;
#pragma unroll
            for (int k = 0; k < 9; k++) {
                float ex = __expf(lv[k]);   // bias already in logit; logits tiny
                se += ex;
                sv = fmaf(ex, nbd[k % 3][j + k / 3], sv);
            }
            orow[2*(pg*8 + j)] = sv * __fdividef(1.f, se);
        }
    }
}

extern "C" void kernel_launch(void* const* d_in, const int* in_sizes, int n_in,
                              void* d_out, int out_size)
{
    const float* x_low = (const float*)d_in[0];
    const float* ctx   = (const float*)d_in[1];
    const float* c1_w  = (const float*)d_in[2];
    const float* c1_b  = (const float*)d_in[3];
    const float* p1_a  = (const float*)d_in[4];
    const float* c2_w  = (const float*)d_in[5];
    const float* c2_b  = (const float*)d_in[6];
    const float* p2_a  = (const float*)d_in[7];
    const float* kp_w  = (const float*)d_in[8];
    const float* kp_b  = (const float*)d_in[9];
    float* out = (float*)d_out;

    conv1_kernel<<<dim3(32, 8), 256>>>(ctx, c1_w, c1_b, p1_a);
    conv2_kernel<<<dim3(32, 8), 256>>>(c2_w, c2_b, p2_a);
    fused_kernel<<<dim3(16, Wn, Bn), 128>>>(x_low, kp_w, kp_b, out);
}